// round 12
// baseline (speedup 1.0000x reference)
#include <cuda_runtime.h>
#include <cstdint>

// Problem constants
#define B_   4
#define N_   2048
#define FIN  256
#define H_   4
#define FO_  64
#define HF   256               // H_*FO_
#define M_   (B_*N_)           // 8192 rows of h
#define NH   (M_*H_)           // 32768 (node, head) pairs

// Scratch (device globals — no allocation allowed)
__device__ float g_h [M_ * HF];                 // h = x@W (3xTF32, ~fp32 exact)
__device__ float g_hr[M_ * HF];                 // h tf32-rounded (attention B operand)
__device__ float g_s[NH], g_dv[NH];
__device__ float g_A1[NH], g_A2[NH], g_E1[NH], g_E2[NH];

// ---------------- helpers ----------------
__device__ __forceinline__ float tf32r(float x) {   // round-to-nearest tf32 (sm_80+ baseline)
    float r; asm("cvt.rna.tf32.f32 %0, %1;" : "=f"(r) : "f"(x)); return r;
}
// m16n8k8 tf32 mma (sm_80+ baseline PTX)
__device__ __forceinline__ void mma8(float* d,
                                     uint32_t a0, uint32_t a1, uint32_t a2, uint32_t a3,
                                     uint32_t b0, uint32_t b1) {
    asm volatile(
        "mma.sync.aligned.m16n8k8.row.col.f32.tf32.tf32.f32 "
        "{%0,%1,%2,%3}, {%4,%5,%6,%7}, {%8,%9}, {%0,%1,%2,%3};"
        : "+f"(d[0]), "+f"(d[1]), "+f"(d[2]), "+f"(d[3])
        : "r"(a0), "r"(a1), "r"(a2), "r"(a3), "r"(b0), "r"(b1));
}
__device__ __forceinline__ uint32_t fbits(float x) { return __float_as_uint(x); }

// ---------------- Kernel 1: h = x @ W via 3xTF32 mma ----------------
// 128x64 block tile, 256 threads = 8 warps; warp wi -> rows m0+wi*16 (m16 tiles).
// K staged 16 at a time as hi/lo tf32 split; D = xh@Wh + xh@Wl + xl@Wh (~fp32).
__global__ __launch_bounds__(256) void gemm_mma(const float* __restrict__ x,
                                                const float* __restrict__ W) {
    __shared__ float xh[16][136], xl[16][136];   // [k][m], pad 136 -> A-frag conflict-free
    __shared__ float wh[16][72],  wl[16][72];    // [k][n], pad 72  -> B-frag conflict-free

    const int t    = threadIdx.x;
    const int wi   = t >> 5;
    const int lane = t & 31;
    const int g    = lane >> 2;     // groupID
    const int c    = lane & 3;      // threadID_in_group
    const int m0   = blockIdx.x * 128;
    const int n0   = blockIdx.y * 64;
    const int mb   = wi * 16;

    float D[8][4];
#pragma unroll
    for (int nt = 0; nt < 8; nt++)
#pragma unroll
        for (int q = 0; q < 4; q++) D[nt][q] = 0.f;

    // staging maps
    const int xrow = t >> 1, xoff = (t & 1) * 8;      // x: 2 thr/row, 8 floats each
    const int wrow = t >> 4, wcol = (t & 15) * 4;     // W: 16 thr/row, 4 floats each

    for (int k0 = 0; k0 < FIN; k0 += 16) {
        float4 xv0 = *(const float4*)(x + (size_t)(m0 + xrow) * FIN + k0 + xoff);
        float4 xv1 = *(const float4*)(x + (size_t)(m0 + xrow) * FIN + k0 + xoff + 4);
        float4 wv  = *(const float4*)(W + (size_t)(k0 + wrow) * HF + n0 + wcol);

        __syncthreads();
        {
            const float* xf0 = (const float*)&xv0;
            const float* xf1 = (const float*)&xv1;
#pragma unroll
            for (int q = 0; q < 4; q++) {
                float f = xf0[q], h = tf32r(f);
                xh[xoff + q][xrow] = h; xl[xoff + q][xrow] = f - h;
            }
#pragma unroll
            for (int q = 0; q < 4; q++) {
                float f = xf1[q], h = tf32r(f);
                xh[xoff + 4 + q][xrow] = h; xl[xoff + 4 + q][xrow] = f - h;
            }
            const float* wf = (const float*)&wv;
#pragma unroll
            for (int q = 0; q < 4; q++) {
                float f = wf[q], h = tf32r(f);
                wh[wrow][wcol + q] = h; wl[wrow][wcol + q] = f - h;
            }
        }
        __syncthreads();

#pragma unroll
        for (int kk2 = 0; kk2 < 2; kk2++) {
            const int kb = kk2 * 8;
            const uint32_t ah0 = fbits(xh[kb + c    ][mb + g]);
            const uint32_t ah1 = fbits(xh[kb + c    ][mb + g + 8]);
            const uint32_t ah2 = fbits(xh[kb + c + 4][mb + g]);
            const uint32_t ah3 = fbits(xh[kb + c + 4][mb + g + 8]);
            const uint32_t al0 = fbits(xl[kb + c    ][mb + g]);
            const uint32_t al1 = fbits(xl[kb + c    ][mb + g + 8]);
            const uint32_t al2 = fbits(xl[kb + c + 4][mb + g]);
            const uint32_t al3 = fbits(xl[kb + c + 4][mb + g + 8]);
#pragma unroll
            for (int nt = 0; nt < 8; nt++) {
                const uint32_t bh0 = fbits(wh[kb + c    ][nt * 8 + g]);
                const uint32_t bh1 = fbits(wh[kb + c + 4][nt * 8 + g]);
                const uint32_t bl0 = fbits(wl[kb + c    ][nt * 8 + g]);
                const uint32_t bl1 = fbits(wl[kb + c + 4][nt * 8 + g]);
                mma8(D[nt], ah0, ah1, ah2, ah3, bh0, bh1);
                mma8(D[nt], ah0, ah1, ah2, ah3, bl0, bl1);
                mma8(D[nt], al0, al1, al2, al3, bh0, bh1);
            }
        }
    }

    // epilogue: D[nt] -> rows m0+mb+g / +8, cols n0+nt*8+c*2
#pragma unroll
    for (int nt = 0; nt < 8; nt++) {
        const size_t r0 = (size_t)(m0 + mb + g)     * HF + n0 + nt * 8 + c * 2;
        const size_t r1 = (size_t)(m0 + mb + g + 8) * HF + n0 + nt * 8 + c * 2;
        *(float2*)(g_h  + r0) = make_float2(D[nt][0], D[nt][1]);
        *(float2*)(g_h  + r1) = make_float2(D[nt][2], D[nt][3]);
        *(float2*)(g_hr + r0) = make_float2(tf32r(D[nt][0]), tf32r(D[nt][1]));
        *(float2*)(g_hr + r1) = make_float2(tf32r(D[nt][2]), tf32r(D[nt][3]));
    }
}

// ---------------- Kernel 2: attention coefficients + exp factors ----------------
__global__ __launch_bounds__(256) void attn_coef_kernel(const float* __restrict__ a_src,
                                                        const float* __restrict__ a_dst) {
    const int nh   = (blockIdx.x * blockDim.x + threadIdx.x) >> 5;
    const int lane = threadIdx.x & 31;
    if (nh >= NH) return;
    const int head = nh & (H_ - 1);

    const float* hrow = g_h + (size_t)nh * FO_;
    const float v0 = hrow[lane];
    const float v1 = hrow[lane + 32];
    const float* as = a_src + head * FO_;
    const float* ad = a_dst + head * FO_;
    float ps = v0 * as[lane] + v1 * as[lane + 32];
    float pd = v0 * ad[lane] + v1 * ad[lane + 32];
#pragma unroll
    for (int o = 16; o > 0; o >>= 1) {
        ps += __shfl_xor_sync(0xffffffffu, ps, o);
        pd += __shfl_xor_sync(0xffffffffu, pd, o);
    }
    if (lane == 0) {
        g_s[nh]  = ps;
        g_A1[nh] = expf(ps);
        g_A2[nh] = expf(0.2f * ps);
        g_dv[nh] = pd;
        g_E1[nh] = expf(pd);
        g_E2[nh] = expf(0.2f * pd);
    }
}

// ---------------- Kernel 3: mma.sync tf32 attention ----------------
// Block = (i-block 128, head, b), 256 threads = 8 warps; warp wi owns rows wi*16..+15.
// Per j-tile of 32 (4 mma k-steps): k-permutation lets thread (g,c) build its
// A-fragment weights (2 rows x 8 contiguous j) straight in registers.
// h-tile has a 65th ones column -> D col 64 = per-row denominator from the
// SAME mma chain as the numerator (exact consistency).
#define TJ  32
#define HSW 73     // h_s row width: 72 used cols + pad -> B-frag LDS conflict-free

__global__ __launch_bounds__(256) void gat_attn_mma(const float* __restrict__ adj,
                                                    float* __restrict__ out) {
    __shared__ __align__(16) float adj_s[128][36];
    __shared__ float h_s[TJ][HSW];
    __shared__ __align__(16) float4 de_s[TJ];
    __shared__ float den_s[8][16];

    const int t    = threadIdx.x;
    const int wi   = t >> 5;
    const int lane = t & 31;
    const int g    = lane >> 2;    // groupID 0..7
    const int c    = lane & 3;     // threadID_in_group 0..3
    const int ib   = blockIdx.x;
    const int head = blockIdx.y;
    const int b    = blockIdx.z;

    // per-thread row coefficients: hi -> row wi*16 + hi*8 + g
    float si[2], A1[2], A2[2];
#pragma unroll
    for (int hi = 0; hi < 2; hi++) {
        const int row = ib * 128 + wi * 16 + hi * 8 + g;
        const int nh  = (b * N_ + row) * H_ + head;
        si[hi] = g_s[nh]; A1[hi] = g_A1[nh]; A2[hi] = g_A2[nh];
    }

    float D[9][4];
#pragma unroll
    for (int nt = 0; nt < 9; nt++)
#pragma unroll
        for (int q = 0; q < 4; q++) D[nt][q] = 0.f;

    // ones/zero pad columns of h_s (written once; staging only touches cols 0..63)
    if (t < TJ) {
        h_s[t][64] = 1.0f;
#pragma unroll
        for (int k = 65; k < HSW; k++) h_s[t][k] = 0.0f;
    }

    const float* adjtile = adj + (size_t)(ib * 128) * N_;
    const float* hbase   = g_hr + (size_t)(b * N_) * HF + head * FO_;

    // staging mappings (256 threads)
    const int xr = t >> 3;          // adj rows xr + k*32 (k=0..3)
    const int xc = (t & 7) * 4;
    const int jr = t >> 4;          // h rows jr + k*16 (k=0..1)
    const int jc = (t & 15) * 4;

    // prologue: prefetch tile 0
    float4 aj[4]; float4 hb[2];
    float nd = 0.f, ne1 = 0.f, ne2 = 0.f;
    {
#pragma unroll
        for (int k = 0; k < 4; k++)
            aj[k] = *(const float4*)(adjtile + (size_t)(xr + k * 32) * N_ + xc);
#pragma unroll
        for (int k = 0; k < 2; k++)
            hb[k] = *(const float4*)(hbase + (size_t)(jr + k * 16) * HF + jc);
        if (t < TJ) {
            const int nh_j = (b * N_ + t) * H_ + head;
            nd = g_dv[nh_j]; ne1 = g_E1[nh_j]; ne2 = g_E2[nh_j];
        }
    }

    for (int jt = 0; jt < N_ / TJ; jt++) {
        __syncthreads();   // previous tile's Phase B / mma done reading smem
#pragma unroll
        for (int k = 0; k < 4; k++)
            *(float4*)&adj_s[xr + k * 32][xc] = aj[k];
#pragma unroll
        for (int k = 0; k < 2; k++) {
            h_s[jr + k * 16][jc + 0] = ((const float*)&hb[k])[0];
            h_s[jr + k * 16][jc + 1] = ((const float*)&hb[k])[1];
            h_s[jr + k * 16][jc + 2] = ((const float*)&hb[k])[2];
            h_s[jr + k * 16][jc + 3] = ((const float*)&hb[k])[3];
        }
        if (t < TJ) de_s[t] = make_float4(nd, ne1, ne2, 0.f);
        __syncthreads();

        // prefetch next tile (LDG latency hidden under Phase B + mma)
        if (jt + 1 < N_ / TJ) {
            const int j0 = (jt + 1) * TJ;
#pragma unroll
            for (int k = 0; k < 4; k++)
                aj[k] = *(const float4*)(adjtile + (size_t)(xr + k * 32) * N_ + j0 + xc);
#pragma unroll
            for (int k = 0; k < 2; k++)
                hb[k] = *(const float4*)(hbase + (size_t)(j0 + jr + k * 16) * HF + jc);
            if (t < TJ) {
                const int nh_j = (b * N_ + j0 + t) * H_ + head;
                nd = g_dv[nh_j]; ne1 = g_E1[nh_j]; ne2 = g_E2[nh_j];
            }
        }

        // ---- Phase B: factored weights straight into A-fragment registers ----
        float4 der[8];
#pragma unroll
        for (int u = 0; u < 8; u++) der[u] = de_s[c * 8 + u];

        float wv[2][8];
#pragma unroll
        for (int hi = 0; hi < 2; hi++) {
            const int rl = wi * 16 + hi * 8 + g;
            float av[8];
            *(float4*)(av)     = *(const float4*)&adj_s[rl][c * 8];
            *(float4*)(av + 4) = *(const float4*)&adj_s[rl][c * 8 + 4];
#pragma unroll
            for (int u = 0; u < 8; u++) {
                const float t0 = si[hi] + der[u].x;
                float w = (t0 > 0.f) ? (A1[hi] * der[u].y) : (A2[hi] * der[u].z);
                w = (av[u] != 0.f) ? w : 0.f;
                wv[hi][u] = tf32r(w);
            }
        }

        // ---- mma phase: D += W * H (k-permuted; both sides use same j(kappa)) ----
#pragma unroll
        for (int s = 0; s < 4; s++) {
            const uint32_t a0 = fbits(wv[0][2 * s]);
            const uint32_t a1 = fbits(wv[1][2 * s]);
            const uint32_t a2 = fbits(wv[0][2 * s + 1]);
            const uint32_t a3 = fbits(wv[1][2 * s + 1]);
            const float* hr0 = &h_s[c * 8 + 2 * s][g];       // b0 j-row
            const float* hr1 = &h_s[c * 8 + 2 * s + 1][g];   // b1 j-row
#pragma unroll
            for (int nt = 0; nt < 9; nt++) {
                const uint32_t b0 = fbits(hr0[nt * 8]);
                const uint32_t b1 = fbits(hr1[nt * 8]);
                mma8(D[nt], a0, a1, a2, a3, b0, b1);
            }
        }
    }

    // ---- epilogue: denominators live in D col 64 (nt=8, c==0 threads) ----
    if (c == 0) {
        den_s[wi][g]     = D[8][0];
        den_s[wi][8 + g] = D[8][2];
    }
    __syncwarp();

#pragma unroll
    for (int hi = 0; hi < 2; hi++) {
        const int rl   = hi * 8 + g;
        const float r  = 1.0f / den_s[wi][rl];
        const int grow = b * N_ + ib * 128 + wi * 16 + rl;
        float* orow    = out + (size_t)grow * HF + head * FO_;
#pragma unroll
        for (int nt = 0; nt < 8; nt++) {
            float2 v;
            v.x = D[nt][hi * 2]     * r;
            v.y = D[nt][hi * 2 + 1] * r;
            *(float2*)(orow + nt * 8 + 2 * c) = v;
        }
    }
}

// ---------------- launch ----------------
extern "C" void kernel_launch(void* const* d_in, const int* in_sizes, int n_in,
                              void* d_out, int out_size) {
    (void)in_sizes; (void)n_in; (void)out_size;
    const float* x     = (const float*)d_in[0];
    const float* adj   = (const float*)d_in[1];
    const float* W     = (const float*)d_in[2];
    const float* a_src = (const float*)d_in[3];
    const float* a_dst = (const float*)d_in[4];
    float* out = (float*)d_out;

    gemm_mma<<<dim3(M_ / 128, HF / 64), 256>>>(x, W);
    attn_coef_kernel<<<(NH * 32) / 256, 256>>>(a_src, a_dst);
    gat_attn_mma<<<dim3(N_ / 128, H_, B_), 256>>>(adj, out);
}

// round 13
// speedup vs baseline: 1.4172x; 1.4172x over previous
#include <cuda_runtime.h>
#include <cstdint>

// Problem constants
#define B_   4
#define N_   2048
#define FIN  256
#define H_   4
#define FO_  64
#define HF   256               // H_*FO_
#define M_   (B_*N_)           // 8192 rows of h
#define NH   (M_*H_)           // 32768 (node, head) pairs

// Scratch (device globals — no allocation allowed)
__device__ float    g_h [M_ * HF];              // h = x@W (3xTF32, ~fp32 exact)
__device__ float    g_hr[M_ * HF];              // h tf32-rounded (attention B operand)
__device__ float    g_s[NH], g_dv[NH];
__device__ float    g_A1[NH], g_A2[NH], g_E1[NH], g_E2[NH];
__device__ uint32_t g_bitsT[(N_ / 32) * N_];    // adj bitmask, transposed: [j_word][i]

// ---------------- helpers ----------------
__device__ __forceinline__ float tf32r(float x) {   // round-to-nearest tf32 (sm_80+ baseline)
    float r; asm("cvt.rna.tf32.f32 %0, %1;" : "=f"(r) : "f"(x)); return r;
}
// m16n8k8 tf32 mma (sm_80+ baseline PTX)
__device__ __forceinline__ void mma8(float* d,
                                     uint32_t a0, uint32_t a1, uint32_t a2, uint32_t a3,
                                     uint32_t b0, uint32_t b1) {
    asm volatile(
        "mma.sync.aligned.m16n8k8.row.col.f32.tf32.tf32.f32 "
        "{%0,%1,%2,%3}, {%4,%5,%6,%7}, {%8,%9}, {%0,%1,%2,%3};"
        : "+f"(d[0]), "+f"(d[1]), "+f"(d[2]), "+f"(d[3])
        : "r"(a0), "r"(a1), "r"(a2), "r"(a3), "r"(b0), "r"(b1));
}
__device__ __forceinline__ uint32_t fbits(float x) { return __float_as_uint(x); }

// ---------------- Kernel 0: pack adj into transposed bitmask ----------------
// warp per row i: lane reads adj[i][jw*32+lane] (coalesced), ballot -> bitsT[jw][i].
__global__ __launch_bounds__(256) void adj_pack_kernel(const float* __restrict__ adj) {
    const int wid  = (blockIdx.x * blockDim.x + threadIdx.x) >> 5;   // row i
    const int lane = threadIdx.x & 31;
    if (wid >= N_) return;
    const float* row = adj + (size_t)wid * N_;
#pragma unroll 4
    for (int jw = 0; jw < N_ / 32; jw++) {
        const uint32_t m = __ballot_sync(0xffffffffu, row[jw * 32 + lane] != 0.f);
        if (lane == 0) g_bitsT[jw * N_ + wid] = m;
    }
}

// ---------------- Kernel 1: h = x @ W via 3xTF32 mma (R12, proven) ----------------
__global__ __launch_bounds__(256) void gemm_mma(const float* __restrict__ x,
                                                const float* __restrict__ W) {
    __shared__ float xh[16][136], xl[16][136];   // [k][m]
    __shared__ float wh[16][72],  wl[16][72];    // [k][n]

    const int t    = threadIdx.x;
    const int wi   = t >> 5;
    const int lane = t & 31;
    const int g    = lane >> 2;
    const int c    = lane & 3;
    const int m0   = blockIdx.x * 128;
    const int n0   = blockIdx.y * 64;
    const int mb   = wi * 16;

    float D[8][4];
#pragma unroll
    for (int nt = 0; nt < 8; nt++)
#pragma unroll
        for (int q = 0; q < 4; q++) D[nt][q] = 0.f;

    const int xrow = t >> 1, xoff = (t & 1) * 8;
    const int wrow = t >> 4, wcol = (t & 15) * 4;

    for (int k0 = 0; k0 < FIN; k0 += 16) {
        float4 xv0 = *(const float4*)(x + (size_t)(m0 + xrow) * FIN + k0 + xoff);
        float4 xv1 = *(const float4*)(x + (size_t)(m0 + xrow) * FIN + k0 + xoff + 4);
        float4 wv  = *(const float4*)(W + (size_t)(k0 + wrow) * HF + n0 + wcol);

        __syncthreads();
        {
            const float* xf0 = (const float*)&xv0;
            const float* xf1 = (const float*)&xv1;
#pragma unroll
            for (int q = 0; q < 4; q++) {
                float f = xf0[q], h = tf32r(f);
                xh[xoff + q][xrow] = h; xl[xoff + q][xrow] = f - h;
            }
#pragma unroll
            for (int q = 0; q < 4; q++) {
                float f = xf1[q], h = tf32r(f);
                xh[xoff + 4 + q][xrow] = h; xl[xoff + 4 + q][xrow] = f - h;
            }
            const float* wf = (const float*)&wv;
#pragma unroll
            for (int q = 0; q < 4; q++) {
                float f = wf[q], h = tf32r(f);
                wh[wrow][wcol + q] = h; wl[wrow][wcol + q] = f - h;
            }
        }
        __syncthreads();

#pragma unroll
        for (int kk2 = 0; kk2 < 2; kk2++) {
            const int kb = kk2 * 8;
            const uint32_t ah0 = fbits(xh[kb + c    ][mb + g]);
            const uint32_t ah1 = fbits(xh[kb + c    ][mb + g + 8]);
            const uint32_t ah2 = fbits(xh[kb + c + 4][mb + g]);
            const uint32_t ah3 = fbits(xh[kb + c + 4][mb + g + 8]);
            const uint32_t al0 = fbits(xl[kb + c    ][mb + g]);
            const uint32_t al1 = fbits(xl[kb + c    ][mb + g + 8]);
            const uint32_t al2 = fbits(xl[kb + c + 4][mb + g]);
            const uint32_t al3 = fbits(xl[kb + c + 4][mb + g + 8]);
#pragma unroll
            for (int nt = 0; nt < 8; nt++) {
                const uint32_t bh0 = fbits(wh[kb + c    ][nt * 8 + g]);
                const uint32_t bh1 = fbits(wh[kb + c + 4][nt * 8 + g]);
                const uint32_t bl0 = fbits(wl[kb + c    ][nt * 8 + g]);
                const uint32_t bl1 = fbits(wl[kb + c + 4][nt * 8 + g]);
                mma8(D[nt], ah0, ah1, ah2, ah3, bh0, bh1);
                mma8(D[nt], ah0, ah1, ah2, ah3, bl0, bl1);
                mma8(D[nt], al0, al1, al2, al3, bh0, bh1);
            }
        }
    }

#pragma unroll
    for (int nt = 0; nt < 8; nt++) {
        const size_t r0 = (size_t)(m0 + mb + g)     * HF + n0 + nt * 8 + c * 2;
        const size_t r1 = (size_t)(m0 + mb + g + 8) * HF + n0 + nt * 8 + c * 2;
        *(float2*)(g_h  + r0) = make_float2(D[nt][0], D[nt][1]);
        *(float2*)(g_h  + r1) = make_float2(D[nt][2], D[nt][3]);
        *(float2*)(g_hr + r0) = make_float2(tf32r(D[nt][0]), tf32r(D[nt][1]));
        *(float2*)(g_hr + r1) = make_float2(tf32r(D[nt][2]), tf32r(D[nt][3]));
    }
}

// ---------------- Kernel 2: attention coefficients + exp factors ----------------
__global__ __launch_bounds__(256) void attn_coef_kernel(const float* __restrict__ a_src,
                                                        const float* __restrict__ a_dst) {
    const int nh   = (blockIdx.x * blockDim.x + threadIdx.x) >> 5;
    const int lane = threadIdx.x & 31;
    if (nh >= NH) return;
    const int head = nh & (H_ - 1);

    const float* hrow = g_h + (size_t)nh * FO_;
    const float v0 = hrow[lane];
    const float v1 = hrow[lane + 32];
    const float* as = a_src + head * FO_;
    const float* ad = a_dst + head * FO_;
    float ps = v0 * as[lane] + v1 * as[lane + 32];
    float pd = v0 * ad[lane] + v1 * ad[lane + 32];
#pragma unroll
    for (int o = 16; o > 0; o >>= 1) {
        ps += __shfl_xor_sync(0xffffffffu, ps, o);
        pd += __shfl_xor_sync(0xffffffffu, pd, o);
    }
    if (lane == 0) {
        g_s[nh]  = ps;
        g_A1[nh] = expf(ps);
        g_A2[nh] = expf(0.2f * ps);
        g_dv[nh] = pd;
        g_E1[nh] = expf(pd);
        g_E2[nh] = expf(0.2f * pd);
    }
}

// ---------------- Kernel 3: mma.sync tf32 attention (R11 shape + bitmask adj) ----------------
// Block = (i-block 128, head, b), 128 threads = 4 warps; warp wi owns rows wi*32..+31.
// adj comes from g_bitsT: 4B/thread/tile (coalesced), 512B smem stage.
// h-tile has a 65th ones column -> D col 64 = per-row denominator from the
// SAME mma chain as the numerator (exact consistency).
#define TJ  32
#define HSW 73     // h_s row width: 72 used cols + pad -> B-frag LDS conflict-free

__global__ __launch_bounds__(128) void gat_attn_mma(float* __restrict__ out) {
    __shared__ float h_s[TJ][HSW];
    __shared__ __align__(16) float4 de_s[TJ];
    __shared__ uint32_t bm_s[128];
    __shared__ float den_s[4][32];

    const int t    = threadIdx.x;
    const int wi   = t >> 5;
    const int lane = t & 31;
    const int g    = lane >> 2;    // groupID 0..7
    const int c    = lane & 3;     // threadID_in_group 0..3
    const int ib   = blockIdx.x;
    const int head = blockIdx.y;
    const int b    = blockIdx.z;

    // per-thread row coefficients: rr -> row wi*32 + (rr>>1)*16 + (rr&1)*8 + g
    float si[4], A1[4], A2[4];
#pragma unroll
    for (int rr = 0; rr < 4; rr++) {
        const int row = ib * 128 + wi * 32 + (rr >> 1) * 16 + (rr & 1) * 8 + g;
        const int nh  = (b * N_ + row) * H_ + head;
        si[rr] = g_s[nh]; A1[rr] = g_A1[nh]; A2[rr] = g_A2[nh];
    }

    float D[2][9][4];
#pragma unroll
    for (int mt = 0; mt < 2; mt++)
#pragma unroll
        for (int nt = 0; nt < 9; nt++)
#pragma unroll
            for (int q = 0; q < 4; q++) D[mt][nt][q] = 0.f;

    // ones/zero pad columns of h_s (written once; staging only touches cols 0..63)
    if (t < TJ) {
        h_s[t][64] = 1.0f;
#pragma unroll
        for (int k = 65; k < HSW; k++) h_s[t][k] = 0.0f;
    }

    const float* hbase = g_hr + (size_t)(b * N_) * HF + head * FO_;

    // staging mappings
    const int jr = t >> 2;          // h row 0..31
    const int jc = (t & 3) * 16;    // h col group

    // prologue: prefetch tile 0
    uint32_t bmr;
    float4 hb[4];
    float nd = 0.f, ne1 = 0.f, ne2 = 0.f;
    {
        bmr = g_bitsT[0 * N_ + ib * 128 + t];
#pragma unroll
        for (int q = 0; q < 4; q++)
            hb[q] = *(const float4*)(hbase + (size_t)jr * HF + jc + 4 * q);
        if (t < TJ) {
            const int nh_j = (b * N_ + t) * H_ + head;
            nd = g_dv[nh_j]; ne1 = g_E1[nh_j]; ne2 = g_E2[nh_j];
        }
    }

    for (int jt = 0; jt < N_ / TJ; jt++) {
        __syncthreads();   // previous tile's Phase B / mma done reading smem
        bm_s[t] = bmr;
#pragma unroll
        for (int q = 0; q < 4; q++) {
            h_s[jr][jc + 4 * q + 0] = ((const float*)&hb[q])[0];
            h_s[jr][jc + 4 * q + 1] = ((const float*)&hb[q])[1];
            h_s[jr][jc + 4 * q + 2] = ((const float*)&hb[q])[2];
            h_s[jr][jc + 4 * q + 3] = ((const float*)&hb[q])[3];
        }
        if (t < TJ) de_s[t] = make_float4(nd, ne1, ne2, 0.f);
        __syncthreads();

        // prefetch next tile (LDG latency hidden under Phase B + mma)
        if (jt + 1 < N_ / TJ) {
            const int j0 = (jt + 1) * TJ;
            bmr = g_bitsT[(jt + 1) * N_ + ib * 128 + t];
#pragma unroll
            for (int q = 0; q < 4; q++)
                hb[q] = *(const float4*)(hbase + (size_t)(j0 + jr) * HF + jc + 4 * q);
            if (t < TJ) {
                const int nh_j = (b * N_ + j0 + t) * H_ + head;
                nd = g_dv[nh_j]; ne1 = g_E1[nh_j]; ne2 = g_E2[nh_j];
            }
        }

        // ---- Phase B: factored weights straight into A-fragment registers ----
        // thread's j set: j = c*8 + u, u = 0..7 (contiguous)
        float4 der[8];
#pragma unroll
        for (int u = 0; u < 8; u++) der[u] = de_s[c * 8 + u];

        float wv[4][8];
#pragma unroll
        for (int rr = 0; rr < 4; rr++) {
            const int rl = wi * 32 + (rr >> 1) * 16 + (rr & 1) * 8 + g;
            const uint32_t m = bm_s[rl] >> (c * 8);
#pragma unroll
            for (int u = 0; u < 8; u++) {
                const float t0 = si[rr] + der[u].x;
                float w = (t0 > 0.f) ? (A1[rr] * der[u].y) : (A2[rr] * der[u].z);
                w = ((m >> u) & 1u) ? w : 0.f;
                wv[rr][u] = tf32r(w);
            }
        }

        // ---- mma phase: D += W * H (k-permuted; both sides use same j(kappa)) ----
#pragma unroll
        for (int s = 0; s < 4; s++) {
            const uint32_t a00 = fbits(wv[0][2 * s]);
            const uint32_t a01 = fbits(wv[1][2 * s]);
            const uint32_t a02 = fbits(wv[0][2 * s + 1]);
            const uint32_t a03 = fbits(wv[1][2 * s + 1]);
            const uint32_t a10 = fbits(wv[2][2 * s]);
            const uint32_t a11 = fbits(wv[3][2 * s]);
            const uint32_t a12 = fbits(wv[2][2 * s + 1]);
            const uint32_t a13 = fbits(wv[3][2 * s + 1]);
            const float* hr0 = &h_s[c * 8 + 2 * s][g];       // b0 j-row
            const float* hr1 = &h_s[c * 8 + 2 * s + 1][g];   // b1 j-row
#pragma unroll
            for (int nt = 0; nt < 9; nt++) {
                const uint32_t b0 = fbits(hr0[nt * 8]);
                const uint32_t b1 = fbits(hr1[nt * 8]);
                mma8(D[0][nt], a00, a01, a02, a03, b0, b1);
                mma8(D[1][nt], a10, a11, a12, a13, b0, b1);
            }
        }
    }

    // ---- epilogue: denominators live in D col 64 (nt=8, c==0 threads) ----
    if (c == 0) {
        den_s[wi][g]      = D[0][8][0];
        den_s[wi][g + 8]  = D[0][8][2];
        den_s[wi][16 + g] = D[1][8][0];
        den_s[wi][24 + g] = D[1][8][2];
    }
    __syncwarp();

#pragma unroll
    for (int mt = 0; mt < 2; mt++)
#pragma unroll
        for (int hi = 0; hi < 2; hi++) {
            const int rl   = mt * 16 + hi * 8 + g;
            const float r  = 1.0f / den_s[wi][rl];
            const int grow = b * N_ + ib * 128 + wi * 32 + rl;
            float* orow    = out + (size_t)grow * HF + head * FO_;
#pragma unroll
            for (int nt = 0; nt < 8; nt++) {
                float2 v;
                v.x = D[mt][nt][hi * 2]     * r;
                v.y = D[mt][nt][hi * 2 + 1] * r;
                *(float2*)(orow + nt * 8 + 2 * c) = v;
            }
        }
}

// ---------------- launch ----------------
extern "C" void kernel_launch(void* const* d_in, const int* in_sizes, int n_in,
                              void* d_out, int out_size) {
    (void)in_sizes; (void)n_in; (void)out_size;
    const float* x     = (const float*)d_in[0];
    const float* adj   = (const float*)d_in[1];
    const float* W     = (const float*)d_in[2];
    const float* a_src = (const float*)d_in[3];
    const float* a_dst = (const float*)d_in[4];
    float* out = (float*)d_out;

    adj_pack_kernel<<<(N_ * 32) / 256, 256>>>(adj);
    gemm_mma<<<dim3(M_ / 128, HF / 64), 256>>>(x, W);
    attn_coef_kernel<<<(NH * 32) / 256, 256>>>(a_src, a_dst);
    gat_attn_mma<<<dim3(N_ / 128, H_, B_), 128>>>(out);
}